// round 12
// baseline (speedup 1.0000x reference)
#include <cuda_runtime.h>

// IntentGCN fused kernel, GB300 (sm_103a). R12: fused warp-shuffle softmax in
// D1, head-group named barriers (D1->D3 without global sync), C folded into
// the same phase. Global barriers/slice: 8 -> 5.
// Shapes: N=32, C=64, T=300, V=25, K=3, H=4, DK=DV=16. 9600 slices.

#define NTH 512
#define GRID 152
#define NSLICE 9600
#define CC 64
#define VV 25
#define TT 300

__device__ int g_counter;

__global__ void reset_counter_kernel() { g_counter = 0; }

constexpr int SW_S = 388;
constexpr int FA_S = 68;
constexpr int GO_S = 388;
constexpr int AW   = 28;   // padded stride for A / fcA / xoT rows
constexpr int FCT_S = 68;  // sfcT row stride

constexpr int OFF_SW  = 0;                       // 64*388 = 24832
constexpr int OFF_SA  = OFF_SW + 64*SW_S;        // 2100
constexpr int OFF_SFC = OFF_SA + 3*VV*AW;        // sfcT: 64*68 = 4352
constexpr int OFF_SC1 = OFF_SFC + 64*FCT_S;
constexpr int OFF_SH1 = OFF_SC1 + 64;
constexpr int OFF_SC2 = OFF_SH1 + 64;
constexpr int OFF_SH2 = OFF_SC2 + 64;
constexpr int OFF_LNG = OFF_SH2 + 64;
constexpr int OFF_LNB = OFF_LNG + 64;
constexpr int OFF_CB  = OFF_LNB + 64;            // 192
constexpr int OFF_FA  = OFF_CB + 192;            // 25*68
constexpr int OFF_QN  = OFF_FA + VV*FA_S;        // 25*68
constexpr int OFF_GO  = OFF_QN + VV*FA_S;        // 25*388
constexpr int OFF_ATT = OFF_GO + VV*GO_S;        // 2500
constexpr int OFF_XOT = OFF_ATT + 2500;          // xoT[e][v]: 64*28 = 1792
constexpr int OFF_FCA = OFF_XOT + 64*AW;         // fcA[c][v]: 64*28 = 1792
constexpr int SMEM_FLOATS = OFF_FCA + 64*AW;     // 51044 floats = 204176 B

__global__ void __launch_bounds__(NTH, 1)
gcn_kernel(const float* __restrict__ x,      const float* __restrict__ A,
           const float* __restrict__ bn1g,   const float* __restrict__ bn1b,
           const float* __restrict__ bn1m,   const float* __restrict__ bn1v,
           const float* __restrict__ conv_w, const float* __restrict__ conv_b,
           const float* __restrict__ ln_g,   const float* __restrict__ ln_b,
           const float* __restrict__ wq,     const float* __restrict__ wk,
           const float* __restrict__ wv,     const float* __restrict__ fc_w,
           const float* __restrict__ gatep,
           const float* __restrict__ bn2g,   const float* __restrict__ bn2b,
           const float* __restrict__ bn2m,   const float* __restrict__ bn2v,
           float* __restrict__ out)
{
    extern __shared__ float sm[];
    float* sW   = sm + OFF_SW;
    float* sA   = sm + OFF_SA;
    float* sfcT = sm + OFF_SFC;
    float* sc1 = sm + OFF_SC1; float* sh1 = sm + OFF_SH1;
    float* sc2 = sm + OFF_SC2; float* sh2 = sm + OFF_SH2;
    float* lng = sm + OFF_LNG; float* lnb = sm + OFF_LNB;
    float* scb = sm + OFF_CB;
    float* fa  = sm + OFF_FA;
    float* qn  = sm + OFF_QN;
    float* go  = sm + OFF_GO;
    float* att = sm + OFF_ATT;
    float* xoT = sm + OFF_XOT;
    float* fcA = sm + OFF_FCA;

    const int tid = threadIdx.x;
    const float gate = __ldg(gatep);

    // ---- one-time weight staging ----
    for (int i = tid; i < 192*64; i += NTH) {
        int o = i >> 6, c = i & 63;
        sW[c*SW_S + o] = conv_w[i];
    }
    for (int i = tid; i < 4096; i += NTH) {
        int c = i >> 6, d = i & 63;
        sW[c*SW_S + 192 + d] = wk[i];
        sW[c*SW_S + 256 + d] = wv[i];
        sW[c*SW_S + 320 + d] = wq[i];
        sfcT[c*FCT_S + d] = fc_w[i];    // sfcT[e][c] = fc_w[e*64+c]
    }
    for (int i = tid; i < 3*VV*AW; i += NTH) {
        int kv = i / AW, w = i - kv * AW;
        sA[i] = (w < VV) ? A[kv * VV + w] : 0.f;
    }
    if (tid < 192) scb[tid] = conv_b[tid];
    if (tid < 64) {
        float s1 = bn1g[tid] * rsqrtf(bn1v[tid] + 1e-5f);
        sc1[tid] = s1; sh1[tid] = bn1b[tid] - bn1m[tid] * s1;
        float s2 = bn2g[tid] * rsqrtf(bn2v[tid] + 1e-5f);
        sc2[tid] = s2; sh2[tid] = bn2b[tid] - bn2m[tid] * s2;
        lng[tid] = ln_g[tid]; lnb[tid] = ln_b[tid];
    }
    __shared__ int s_slice;
    __syncthreads();

    const int wid = tid >> 5, lane = tid & 31;

    for (;;) {
        if (tid == 0) s_slice = atomicAdd(&g_counter, 1);
        __syncthreads();               // (1) also fences previous slice's readers
        const int slice = s_slice;
        if (slice >= NSLICE) break;
        const int n = slice / TT, t = slice - n * TT;

        // ---- Step A: load x slice, BN1, transpose -> fa[v][c] ----
        {
            const float* xs = x + ((long)n * CC * TT + t) * VV;
            for (int i = tid; i < CC * VV; i += NTH) {
                int c = i / VV, v = i - c * VV;
                float val = xs[(long)c * TT * VV + v];
                fa[v * FA_S + c] = fmaf(val, sc1[c], sh1[c]);
            }
        }
        __syncthreads();               // (2)

        // ---- Step A2: LayerNorm per joint -> qn[v][c] ----
        for (int v = wid; v < VV; v += 16) {
            float a0 = fa[v * FA_S + lane];
            float a1 = fa[v * FA_S + 32 + lane];
            float s = a0 + a1, sq = a0 * a0 + a1 * a1;
            #pragma unroll
            for (int off = 16; off; off >>= 1) {
                s  += __shfl_xor_sync(0xffffffffu, s, off);
                sq += __shfl_xor_sync(0xffffffffu, sq, off);
            }
            float mu = s * (1.f / 64.f);
            float var = sq * (1.f / 64.f) - mu * mu;
            float rstd = rsqrtf(var + 1e-6f);
            qn[v * FA_S + lane]      = fmaf((a0 - mu) * rstd, lng[lane],      lnb[lane]);
            qn[v * FA_S + 32 + lane] = fmaf((a1 - mu) * rstd, lng[lane + 32], lnb[lane + 32]);
        }
        __syncthreads();               // (3)

        // ---- Step B: combined GEMM [25 x 64] @ [64 x 384] -> go[v][j] ----
        if (tid < 480) {
            const int vg = tid / 96;
            const int jg = tid - vg * 96;
            const int j0 = jg * 4;
            const float* opb = ((j0 >= 320) ? qn : fa) + vg * 5 * FA_S;
            float acc[5][4];
            #pragma unroll
            for (int vi = 0; vi < 5; vi++)
                #pragma unroll
                for (int jj = 0; jj < 4; jj++) acc[vi][jj] = 0.f;

            #pragma unroll 4
            for (int c = 0; c < CC; c += 4) {
                float4 f4[5];
                #pragma unroll
                for (int vi = 0; vi < 5; vi++)
                    f4[vi] = *(const float4*)(opb + vi * FA_S + c);
                #pragma unroll
                for (int i = 0; i < 4; i++) {
                    float4 w4 = *(const float4*)(sW + (c + i) * SW_S + j0);
                    #pragma unroll
                    for (int vi = 0; vi < 5; vi++) {
                        float f = (i == 0) ? f4[vi].x : (i == 1) ? f4[vi].y
                                : (i == 2) ? f4[vi].z : f4[vi].w;
                        acc[vi][0] = fmaf(f, w4.x, acc[vi][0]);
                        acc[vi][1] = fmaf(f, w4.y, acc[vi][1]);
                        acc[vi][2] = fmaf(f, w4.z, acc[vi][2]);
                        acc[vi][3] = fmaf(f, w4.w, acc[vi][3]);
                    }
                }
            }
            float4 b4 = make_float4(0.f, 0.f, 0.f, 0.f);
            if (j0 < 192) b4 = *(const float4*)(scb + j0);
            #pragma unroll
            for (int vi = 0; vi < 5; vi++) {
                float4 r;
                r.x = acc[vi][0] + b4.x; r.y = acc[vi][1] + b4.y;
                r.z = acc[vi][2] + b4.z; r.w = acc[vi][3] + b4.w;
                *(float4*)(go + (vg * 5 + vi) * GO_S + j0) = r;
            }
        }
        __syncthreads();               // (4)

        // ===== mega-phase: D1+softmax -> named bar -> D3 -> C =====
        const int h = wid >> 2;        // head group: warps 4h..4h+3

        // ---- D1: scores for head h, rows qi = (wid&3) + 4m; lane = kj.
        //      Softmax fused via warp shuffles (lane holds one kj of the row).
        {
            const int r = wid & 3;
            float4 k0 = make_float4(0.f,0.f,0.f,0.f), k1 = k0, k2 = k0, k3 = k0;
            if (lane < VV) {
                const float* kp = go + lane * GO_S + 192 + h * 16;
                k0 = *(const float4*)(kp);
                k1 = *(const float4*)(kp + 4);
                k2 = *(const float4*)(kp + 8);
                k3 = *(const float4*)(kp + 12);
            }
            for (int qi = r; qi < VV; qi += 4) {
                const float* qp = go + qi * GO_S + 320 + h * 16;
                float4 q0 = *(const float4*)(qp);
                float4 q1 = *(const float4*)(qp + 4);
                float4 q2 = *(const float4*)(qp + 8);
                float4 q3 = *(const float4*)(qp + 12);
                float sc = -1e30f;
                if (lane < VV) {
                    float acc = q0.x*k0.x + q0.y*k0.y + q0.z*k0.z + q0.w*k0.w;
                    acc = fmaf(q1.x, k1.x, acc); acc = fmaf(q1.y, k1.y, acc);
                    acc = fmaf(q1.z, k1.z, acc); acc = fmaf(q1.w, k1.w, acc);
                    acc = fmaf(q2.x, k2.x, acc); acc = fmaf(q2.y, k2.y, acc);
                    acc = fmaf(q2.z, k2.z, acc); acc = fmaf(q2.w, k2.w, acc);
                    acc = fmaf(q3.x, k3.x, acc); acc = fmaf(q3.y, k3.y, acc);
                    acc = fmaf(q3.z, k3.z, acc); acc = fmaf(q3.w, k3.w, acc);
                    sc = acc * 0.25f;
                }
                // warp softmax over the 25 valid lanes
                float m = sc;
                #pragma unroll
                for (int off = 16; off; off >>= 1)
                    m = fmaxf(m, __shfl_xor_sync(0xffffffffu, m, off));
                float e = (lane < VV) ? __expf(sc - m) : 0.f;
                float ssum = e;
                #pragma unroll
                for (int off = 16; off; off >>= 1)
                    ssum += __shfl_xor_sync(0xffffffffu, ssum, off);
                if (lane < VV)
                    att[(h * VV + qi) * VV + lane] = e * (1.f / ssum);
            }
        }
        // named barrier: only the 4 warps of this head need to agree
        asm volatile("bar.sync %0, 128;" :: "r"(h + 1) : "memory");

        // ---- D3: xoT[e][v] = sum_j attn[h,v,j] * vv[j][e]; e0 = wid*4 ----
        {
            const int e0 = wid * 4;    // e0>>4 == h by construction
            if (lane < VV) {
                const float* ap = att + (h * VV + lane) * VV;
                const float* gp = go + 256 + e0;
                float4 acc = make_float4(0.f, 0.f, 0.f, 0.f);
                #pragma unroll
                for (int j = 0; j < VV; j++) {
                    float a = ap[j];
                    float4 v4 = *(const float4*)(gp + j * GO_S);   // broadcast
                    acc.x = fmaf(a, v4.x, acc.x);
                    acc.y = fmaf(a, v4.y, acc.y);
                    acc.z = fmaf(a, v4.z, acc.z);
                    acc.w = fmaf(a, v4.w, acc.w);
                }
                xoT[(e0 + 0) * AW + lane] = acc.x;
                xoT[(e0 + 1) * AW + lane] = acc.y;
                xoT[(e0 + 2) * AW + lane] = acc.z;
                xoT[(e0 + 3) * AW + lane] = acc.w;
            }
        }

        // ---- C: fcA[c][w] for c in [wid*4, wid*4+4); lane=(ci,wg) ----
        {
            const int ci = lane >> 3, wg = lane & 7;
            if (wg < 7) {
                const int c = wid * 4 + ci;
                const int w0 = wg * 4;
                float4 acc = make_float4(0.f, 0.f, 0.f, 0.f);
                #pragma unroll
                for (int k = 0; k < 3; k++) {
                    const float* gp = go + k * 64 + c;
                    const float* ap = sA + k * VV * AW + w0;
                    #pragma unroll
                    for (int v = 0; v < VV; v++) {
                        float g = gp[v * GO_S];                    // 1 wf (4 addr)
                        float4 a4 = *(const float4*)(ap + v * AW); // 1 wf (7 addr)
                        acc.x = fmaf(g, a4.x, acc.x);
                        acc.y = fmaf(g, a4.y, acc.y);
                        acc.z = fmaf(g, a4.z, acc.z);
                        acc.w = fmaf(g, a4.w, acc.w);
                    }
                }
                *(float4*)(fcA + c * AW + w0) = acc;
            }
        }
        __syncthreads();               // (5)

        // ---- Step E: out = relu(bn2((xo@fc + fa)*gate + fcA)*0.5) ----
        {
            const int c0 = wid * 4;
            if (lane < VV) {
                const int v = lane;
                float4 acc = make_float4(0.f, 0.f, 0.f, 0.f);
                const float* xp = xoT + v;
                const float* wp = sfcT + c0;
                #pragma unroll 16
                for (int e = 0; e < CC; e++) {
                    float xval = xp[e * AW];
                    float4 w4 = *(const float4*)(wp + e * FCT_S);  // broadcast
                    acc.x = fmaf(xval, w4.x, acc.x);
                    acc.y = fmaf(xval, w4.y, acc.y);
                    acc.z = fmaf(xval, w4.z, acc.z);
                    acc.w = fmaf(xval, w4.w, acc.w);
                }
                float4 res = *(const float4*)(fa + v * FA_S + c0);
                float* os = out + ((long)n * CC * TT + t) * VV;
                #pragma unroll
                for (int i = 0; i < 4; i++) {
                    float fa_ = (i == 0) ? acc.x + res.x : (i == 1) ? acc.y + res.y
                              : (i == 2) ? acc.z + res.z : acc.w + res.w;
                    float f = (fa_ * gate + fcA[(c0 + i) * AW + v]) * 0.5f;
                    float o = fmaf(f, sc2[c0 + i], sh2[c0 + i]);
                    os[(long)(c0 + i) * TT * VV + v] = fmaxf(o, 0.f);
                }
            }
        }
        // next-iteration top __syncthreads() protects fa/xoT/fcA/att reuse
    }
}

extern "C" void kernel_launch(void* const* d_in, const int* in_sizes, int n_in,
                              void* d_out, int out_size)
{
    (void)in_sizes; (void)n_in; (void)out_size;
    const float* x      = (const float*)d_in[0];
    const float* A      = (const float*)d_in[1];
    const float* bn1g   = (const float*)d_in[2];
    const float* bn1b   = (const float*)d_in[3];
    const float* bn1m   = (const float*)d_in[4];
    const float* bn1v   = (const float*)d_in[5];
    const float* conv_w = (const float*)d_in[6];
    const float* conv_b = (const float*)d_in[7];
    const float* ln_g   = (const float*)d_in[8];
    const float* ln_b   = (const float*)d_in[9];
    const float* wq     = (const float*)d_in[10];
    const float* wk     = (const float*)d_in[11];
    const float* wv     = (const float*)d_in[12];
    const float* fc_w   = (const float*)d_in[13];
    const float* gate   = (const float*)d_in[14];
    const float* bn2g   = (const float*)d_in[15];
    const float* bn2b   = (const float*)d_in[16];
    const float* bn2m   = (const float*)d_in[17];
    const float* bn2v   = (const float*)d_in[18];

    const int smem_bytes = SMEM_FLOATS * 4;
    cudaFuncSetAttribute(gcn_kernel, cudaFuncAttributeMaxDynamicSharedMemorySize, smem_bytes);

    reset_counter_kernel<<<1, 1>>>();
    gcn_kernel<<<GRID, NTH, smem_bytes>>>(
        x, A, bn1g, bn1b, bn1m, bn1v, conv_w, conv_b, ln_g, ln_b,
        wq, wk, wv, fc_w, gate, bn2g, bn2b, bn2m, bn2v, (float*)d_out);
}

// round 13
// speedup vs baseline: 1.1319x; 1.1319x over previous
#include <cuda_runtime.h>

// IntentGCN fused kernel, GB300 (sm_103a). R13: R11 structure (verified 843us)
// + packed fma.rn.f32x2 in B/C/D1/D3/E (halves fp32 FMA issue slots).
// Shapes: N=32, C=64, T=300, V=25, K=3, H=4, DK=DV=16. 9600 slices.

#define NTH 512
#define GRID 152
#define NSLICE 9600
#define CC 64
#define VV 25
#define TT 300

typedef unsigned long long u64;

__device__ __forceinline__ u64 fma2(u64 a, u64 b, u64 c) {
    u64 d; asm("fma.rn.f32x2 %0, %1, %2, %3;" : "=l"(d) : "l"(a), "l"(b), "l"(c));
    return d;
}
__device__ __forceinline__ u64 add2(u64 a, u64 b) {
    u64 d; asm("add.rn.f32x2 %0, %1, %2;" : "=l"(d) : "l"(a), "l"(b));
    return d;
}
__device__ __forceinline__ u64 pack2(float v) {
    u64 d; asm("mov.b64 %0, {%1, %1};" : "=l"(d) : "f"(v));
    return d;
}
__device__ __forceinline__ float2 unpk2(u64 d) {
    float2 f; asm("mov.b64 {%0, %1}, %2;" : "=f"(f.x), "=f"(f.y) : "l"(d));
    return f;
}

__device__ int g_counter;

__global__ void reset_counter_kernel() { g_counter = 0; }

constexpr int SW_S = 388;
constexpr int FA_S = 68;
constexpr int GO_S = 388;
constexpr int AW   = 28;   // padded stride for A / fcA / xoT rows
constexpr int FCT_S = 68;  // sfcT row stride

constexpr int OFF_SW  = 0;                       // 64*388 = 24832
constexpr int OFF_SA  = OFF_SW + 64*SW_S;        // 2100
constexpr int OFF_SFC = OFF_SA + 3*VV*AW;        // sfcT: 64*68 = 4352
constexpr int OFF_SC1 = OFF_SFC + 64*FCT_S;
constexpr int OFF_SH1 = OFF_SC1 + 64;
constexpr int OFF_SC2 = OFF_SH1 + 64;
constexpr int OFF_SH2 = OFF_SC2 + 64;
constexpr int OFF_LNG = OFF_SH2 + 64;
constexpr int OFF_LNB = OFF_LNG + 64;
constexpr int OFF_CB  = OFF_LNB + 64;            // 192
constexpr int OFF_FA  = OFF_CB + 192;            // 25*68
constexpr int OFF_QN  = OFF_FA + VV*FA_S;        // 25*68
constexpr int OFF_GO  = OFF_QN + VV*FA_S;        // 25*388
constexpr int OFF_ATT = OFF_GO + VV*GO_S;        // 2500
constexpr int OFF_XOT = OFF_ATT + 2500;          // xoT[e][v]: 64*28 = 1792
constexpr int OFF_FCA = OFF_XOT + 64*AW;         // fcA[c][v]: 64*28 = 1792
constexpr int SMEM_FLOATS = OFF_FCA + 64*AW;     // 51044 floats = 204176 B

__global__ void __launch_bounds__(NTH, 1)
gcn_kernel(const float* __restrict__ x,      const float* __restrict__ A,
           const float* __restrict__ bn1g,   const float* __restrict__ bn1b,
           const float* __restrict__ bn1m,   const float* __restrict__ bn1v,
           const float* __restrict__ conv_w, const float* __restrict__ conv_b,
           const float* __restrict__ ln_g,   const float* __restrict__ ln_b,
           const float* __restrict__ wq,     const float* __restrict__ wk,
           const float* __restrict__ wv,     const float* __restrict__ fc_w,
           const float* __restrict__ gatep,
           const float* __restrict__ bn2g,   const float* __restrict__ bn2b,
           const float* __restrict__ bn2m,   const float* __restrict__ bn2v,
           float* __restrict__ out)
{
    extern __shared__ float sm[];
    float* sW   = sm + OFF_SW;
    float* sA   = sm + OFF_SA;
    float* sfcT = sm + OFF_SFC;
    float* sc1 = sm + OFF_SC1; float* sh1 = sm + OFF_SH1;
    float* sc2 = sm + OFF_SC2; float* sh2 = sm + OFF_SH2;
    float* lng = sm + OFF_LNG; float* lnb = sm + OFF_LNB;
    float* scb = sm + OFF_CB;
    float* fa  = sm + OFF_FA;
    float* qn  = sm + OFF_QN;
    float* go  = sm + OFF_GO;
    float* att = sm + OFF_ATT;
    float* xoT = sm + OFF_XOT;
    float* fcA = sm + OFF_FCA;

    const int tid = threadIdx.x;
    const float gate = __ldg(gatep);

    // ---- one-time weight staging ----
    for (int i = tid; i < 192*64; i += NTH) {
        int o = i >> 6, c = i & 63;
        sW[c*SW_S + o] = conv_w[i];
    }
    for (int i = tid; i < 4096; i += NTH) {
        int c = i >> 6, d = i & 63;
        sW[c*SW_S + 192 + d] = wk[i];
        sW[c*SW_S + 256 + d] = wv[i];
        sW[c*SW_S + 320 + d] = wq[i];
        sfcT[c*FCT_S + d] = fc_w[i];    // sfcT[e][c] = fc_w[e*64+c]
    }
    for (int i = tid; i < 3*VV*AW; i += NTH) {
        int kv = i / AW, w = i - kv * AW;
        sA[i] = (w < VV) ? A[kv * VV + w] : 0.f;
    }
    if (tid < 192) scb[tid] = conv_b[tid];
    if (tid < 64) {
        float s1 = bn1g[tid] * rsqrtf(bn1v[tid] + 1e-5f);
        sc1[tid] = s1; sh1[tid] = bn1b[tid] - bn1m[tid] * s1;
        float s2 = bn2g[tid] * rsqrtf(bn2v[tid] + 1e-5f);
        sc2[tid] = s2; sh2[tid] = bn2b[tid] - bn2m[tid] * s2;
        lng[tid] = ln_g[tid]; lnb[tid] = ln_b[tid];
    }
    __shared__ int s_slice;
    __syncthreads();

    const int wid = tid >> 5, lane = tid & 31;

    for (;;) {
        if (tid == 0) s_slice = atomicAdd(&g_counter, 1);
        __syncthreads();               // also fences previous slice's readers
        const int slice = s_slice;
        if (slice >= NSLICE) break;
        const int n = slice / TT, t = slice - n * TT;

        // ---- Step A: load x slice, BN1, transpose -> fa[v][c] ----
        {
            const float* xs = x + ((long)n * CC * TT + t) * VV;
            for (int i = tid; i < CC * VV; i += NTH) {
                int c = i / VV, v = i - c * VV;
                float val = xs[(long)c * TT * VV + v];
                fa[v * FA_S + c] = fmaf(val, sc1[c], sh1[c]);
            }
        }
        __syncthreads();

        // ---- Step A2: LayerNorm per joint -> qn[v][c] ----
        for (int v = wid; v < VV; v += 16) {
            float a0 = fa[v * FA_S + lane];
            float a1 = fa[v * FA_S + 32 + lane];
            float s = a0 + a1, sq = a0 * a0 + a1 * a1;
            #pragma unroll
            for (int off = 16; off; off >>= 1) {
                s  += __shfl_xor_sync(0xffffffffu, s, off);
                sq += __shfl_xor_sync(0xffffffffu, sq, off);
            }
            float mu = s * (1.f / 64.f);
            float var = sq * (1.f / 64.f) - mu * mu;
            float rstd = rsqrtf(var + 1e-6f);
            qn[v * FA_S + lane]      = fmaf((a0 - mu) * rstd, lng[lane],      lnb[lane]);
            qn[v * FA_S + 32 + lane] = fmaf((a1 - mu) * rstd, lng[lane + 32], lnb[lane + 32]);
        }
        __syncthreads();

        // ---- Step B: combined GEMM [25 x 64] @ [64 x 384] -> go[v][j] ----
        // 480 threads: vg owns 5 v-rows, jg owns 4 j-cols (2 f32x2 pairs).
        if (tid < 480) {
            const int vg = tid / 96;
            const int jg = tid - vg * 96;
            const int j0 = jg * 4;
            const float* opb = ((j0 >= 320) ? qn : fa) + vg * 5 * FA_S;
            u64 acc2[5][2];
            #pragma unroll
            for (int vi = 0; vi < 5; vi++) { acc2[vi][0] = 0ull; acc2[vi][1] = 0ull; }

            #pragma unroll 4
            for (int c = 0; c < CC; c += 4) {
                float4 f4[5];
                #pragma unroll
                for (int vi = 0; vi < 5; vi++)
                    f4[vi] = *(const float4*)(opb + vi * FA_S + c);
                #pragma unroll
                for (int i = 0; i < 4; i++) {
                    ulonglong2 w2 = *(const ulonglong2*)(sW + (c + i) * SW_S + j0);
                    #pragma unroll
                    for (int vi = 0; vi < 5; vi++) {
                        float f = (i == 0) ? f4[vi].x : (i == 1) ? f4[vi].y
                                : (i == 2) ? f4[vi].z : f4[vi].w;
                        u64 fp = pack2(f);
                        acc2[vi][0] = fma2(fp, w2.x, acc2[vi][0]);
                        acc2[vi][1] = fma2(fp, w2.y, acc2[vi][1]);
                    }
                }
            }
            ulonglong2 b2;
            b2.x = 0ull; b2.y = 0ull;
            if (j0 < 192) b2 = *(const ulonglong2*)(scb + j0);
            #pragma unroll
            for (int vi = 0; vi < 5; vi++) {
                ulonglong2 r2;
                r2.x = add2(acc2[vi][0], b2.x);
                r2.y = add2(acc2[vi][1], b2.y);
                *(ulonglong2*)(go + (vg * 5 + vi) * GO_S + j0) = r2;
            }
        }
        __syncthreads();

        // ---- Step C: fixed-branch A contraction (448 threads) ----
        if (tid < 448) {
            const int c = tid / 7, wg = tid - (tid / 7) * 7, w0 = wg * 4;
            u64 acc2[2] = {0ull, 0ull};
            #pragma unroll
            for (int k = 0; k < 3; k++) {
                const float* gp = go + k * 64 + c;
                const float* ap = sA + k * VV * AW + w0;
                #pragma unroll
                for (int v = 0; v < VV; v++) {
                    u64 g2 = pack2(gp[v * GO_S]);
                    ulonglong2 a2 = *(const ulonglong2*)(ap + v * AW);
                    acc2[0] = fma2(g2, a2.x, acc2[0]);
                    acc2[1] = fma2(g2, a2.y, acc2[1]);
                }
            }
            *(ulonglong2*)(fcA + c * AW + w0) = *(ulonglong2*)acc2;
        }
        // ---- Step D1: attention scores; K-fragments in registers (f32x2) ----
        {
            const int h = wid >> 2, r = wid & 3;
            u64 kk[8];
            #pragma unroll
            for (int i = 0; i < 8; i++) kk[i] = 0ull;
            if (lane < VV) {
                const ulonglong2* kp = (const ulonglong2*)(go + lane * GO_S + 192 + h * 16);
                ulonglong2 ka = kp[0], kb = kp[1], kc = kp[2], kd = kp[3];
                kk[0] = ka.x; kk[1] = ka.y; kk[2] = kb.x; kk[3] = kb.y;
                kk[4] = kc.x; kk[5] = kc.y; kk[6] = kd.x; kk[7] = kd.y;
            }
            for (int qi = r; qi < VV; qi += 4) {
                const ulonglong2* qp = (const ulonglong2*)(go + qi * GO_S + 320 + h * 16);
                ulonglong2 qa = qp[0], qb = qp[1], qc = qp[2], qd = qp[3];
                if (lane < VV) {
                    u64 a2 = 0ull;
                    a2 = fma2(qa.x, kk[0], a2); a2 = fma2(qa.y, kk[1], a2);
                    a2 = fma2(qb.x, kk[2], a2); a2 = fma2(qb.y, kk[3], a2);
                    a2 = fma2(qc.x, kk[4], a2); a2 = fma2(qc.y, kk[5], a2);
                    a2 = fma2(qd.x, kk[6], a2); a2 = fma2(qd.y, kk[7], a2);
                    float2 p = unpk2(a2);
                    att[(h * VV + qi) * VV + lane] = (p.x + p.y) * 0.25f;
                }
            }
        }
        __syncthreads();

        // ---- Step D2: softmax over last dim (100 rows of 25) ----
        if (tid < 100) {
            float* row = att + tid * VV;
            float m = row[0];
            #pragma unroll
            for (int j = 1; j < VV; j++) m = fmaxf(m, row[j]);
            float e[VV]; float s = 0.f;
            #pragma unroll
            for (int j = 0; j < VV; j++) { e[j] = __expf(row[j] - m); s += e[j]; }
            float inv = 1.f / s;
            #pragma unroll
            for (int j = 0; j < VV; j++) row[j] = e[j] * inv;
        }
        __syncthreads();

        // ---- Step D3: xoT[e][v] = sum_j attn[h,v,j] * vv[j][e] (f32x2) ----
        {
            const int e0 = wid * 4, h = e0 >> 4;
            if (lane < VV) {
                const float* ap = att + (h * VV + lane) * VV;
                const float* gp = go + 256 + e0;
                u64 acc2[2] = {0ull, 0ull};
                #pragma unroll
                for (int j = 0; j < VV; j++) {
                    u64 a2 = pack2(ap[j]);
                    ulonglong2 v2 = *(const ulonglong2*)(gp + j * GO_S);  // broadcast
                    acc2[0] = fma2(a2, v2.x, acc2[0]);
                    acc2[1] = fma2(a2, v2.y, acc2[1]);
                }
                float2 p01 = unpk2(acc2[0]), p23 = unpk2(acc2[1]);
                xoT[(e0 + 0) * AW + lane] = p01.x;
                xoT[(e0 + 1) * AW + lane] = p01.y;
                xoT[(e0 + 2) * AW + lane] = p23.x;
                xoT[(e0 + 3) * AW + lane] = p23.y;
            }
        }
        __syncthreads();

        // ---- Step E: out = relu(bn2((xo@fc + fa)*gate + fcA)*0.5) (f32x2) ----
        {
            const int c0 = wid * 4;
            if (lane < VV) {
                const int v = lane;
                u64 acc2[2] = {0ull, 0ull};
                const float* xp = xoT + v;
                const float* wp = sfcT + c0;
                #pragma unroll 16
                for (int e = 0; e < CC; e++) {
                    u64 x2 = pack2(xp[e * AW]);
                    ulonglong2 w2 = *(const ulonglong2*)(wp + e * FCT_S);  // broadcast
                    acc2[0] = fma2(x2, w2.x, acc2[0]);
                    acc2[1] = fma2(x2, w2.y, acc2[1]);
                }
                float2 p01 = unpk2(acc2[0]), p23 = unpk2(acc2[1]);
                float accv[4] = {p01.x, p01.y, p23.x, p23.y};
                float4 res = *(const float4*)(fa + v * FA_S + c0);
                float resv[4] = {res.x, res.y, res.z, res.w};
                float* os = out + ((long)n * CC * TT + t) * VV;
                #pragma unroll
                for (int i = 0; i < 4; i++) {
                    float fa_ = accv[i] + resv[i];
                    float f = (fa_ * gate + fcA[(c0 + i) * AW + v]) * 0.5f;
                    float o = fmaf(f, sc2[c0 + i], sh2[c0 + i]);
                    os[(long)(c0 + i) * TT * VV + v] = fmaxf(o, 0.f);
                }
            }
        }
        // next-iteration top __syncthreads() protects fa/xoT/fcA reuse
    }
}

extern "C" void kernel_launch(void* const* d_in, const int* in_sizes, int n_in,
                              void* d_out, int out_size)
{
    (void)in_sizes; (void)n_in; (void)out_size;
    const float* x      = (const float*)d_in[0];
    const float* A      = (const float*)d_in[1];
    const float* bn1g   = (const float*)d_in[2];
    const float* bn1b   = (const float*)d_in[3];
    const float* bn1m   = (const float*)d_in[4];
    const float* bn1v   = (const float*)d_in[5];
    const float* conv_w = (const float*)d_in[6];
    const float* conv_b = (const float*)d_in[7];
    const float* ln_g   = (const float*)d_in[8];
    const float* ln_b   = (const float*)d_in[9];
    const float* wq     = (const float*)d_in[10];
    const float* wk     = (const float*)d_in[11];
    const float* wv     = (const float*)d_in[12];
    const float* fc_w   = (const float*)d_in[13];
    const float* gate   = (const float*)d_in[14];
    const float* bn2g   = (const float*)d_in[15];
    const float* bn2b   = (const float*)d_in[16];
    const float* bn2m   = (const float*)d_in[17];
    const float* bn2v   = (const float*)d_in[18];

    const int smem_bytes = SMEM_FLOATS * 4;
    cudaFuncSetAttribute(gcn_kernel, cudaFuncAttributeMaxDynamicSharedMemorySize, smem_bytes);

    reset_counter_kernel<<<1, 1>>>();
    gcn_kernel<<<GRID, NTH, smem_bytes>>>(
        x, A, bn1g, bn1b, bn1m, bn1v, conv_w, conv_b, ln_g, ln_b,
        wq, wk, wv, fc_w, gate, bn2g, bn2b, bn2m, bn2v, (float*)d_out);
}